// round 4
// baseline (speedup 1.0000x reference)
#include <cuda_runtime.h>

#define LRATE 0.25f
#define NIT 20
#define MPAD 48

// Persistent device scratch (rewritten deterministically every launch)
__device__ float gM[NIT + 1][MPAD];      // per-iteration sums
__device__ float gTheta[NIT + 1][12];    // theta trajectory
__device__ float gLam[NIT][12];          // adjoints: gLam[k] = lambda_{k+1}

// theta layout [12]: t1 (0..3 row-major), b1 (4,5), t2 (6..9 row-major), b2 (10,11)
// gM layout:
//  0..3   M1_{ab} = sum p_a h_b
//  4..7   M2_{ab} = sum p_a s_b
//  8..15  M3_{abc}= sum p_a s_b z_c
// 16..17  T4_b    = sum w_b h_b s_b          (w_b = t1[0][b] px + t1[1][b] py at pass-k theta)
// 18..21  T5_bc   = sum w_b h_b s_b z_c
// 22..27  T6_b,(ce)= sum w_b h_b s_b z_c z_e (sym pair index c+e)
// 40..41  Sp_a    = sum p_a  (theta-independent; written by pass 0 only)

__device__ __forceinline__ float ftanh(float x) {
    float e = __expf(-2.0f * fabsf(x));
    float r = __fdividef(1.0f - e, 1.0f + e);
    return copysignf(r, x);
}

__device__ __forceinline__ void sym4mv(const float* __restrict__ A, const float* v, float* y) {
#pragma unroll
    for (int r = 0; r < 4; ++r) {
        float s = 0.f;
#pragma unroll
        for (int c = 0; c < 4; ++c) s += 0.5f * (A[4 * r + c] + A[4 * c + r]) * v[c];
        y[r] = s;
    }
}
__device__ __forceinline__ void sym2mv(const float* __restrict__ A, const float* v, float* y) {
#pragma unroll
    for (int r = 0; r < 2; ++r) {
        float s = 0.f;
#pragma unroll
        for (int c = 0; c < 2; ++c) s += 0.5f * (A[2 * r + c] + A[2 * c + r]) * v[c];
        y[r] = s;
    }
}

// G = dL/dtheta from forward moments (M[0..15]) + Sp
__device__ __forceinline__ void compute_G(const float* th, const float* M,
                                          float sp0, float sp1,
                                          const float* __restrict__ invK,
                                          const float* __restrict__ invKb,
                                          float inv2K, float* G) {
    float y[4], yb[2];
    sym4mv(invK, th, y);
#pragma unroll
    for (int r = 0; r < 4; ++r) G[r] = y[r] - inv2K * M[r];
    sym2mv(invKb, th + 4, yb);
    G[4] = yb[0] - inv2K * sp0;
    G[5] = yb[1] - inv2K * sp1;
    float v2[4] = {th[6] - 1.f, th[7], th[8], th[9] - 1.f};
    sym4mv(invK, v2, y);
#pragma unroll
    for (int b = 0; b < 2; ++b)
#pragma unroll
        for (int c = 0; c < 2; ++c) {
            float pot = th[b] * M[8 + 2 * b + c] + th[2 + b] * M[8 + 4 + 2 * b + c];
            G[6 + 2 * b + c] = y[2 * b + c] - inv2K * pot;
        }
    sym2mv(invKb, th + 10, yb);
#pragma unroll
    for (int b = 0; b < 2; ++b) {
        float pot = th[b] * M[4 + b] + th[2 + b] * M[4 + 2 + b];
        G[10 + b] = yb[b] - inv2K * pot;
    }
}

__global__ void zero_moments_kernel() {
    int t = threadIdx.x;
    if (t < (NIT + 1) * MPAD) ((float*)gM)[t] = 0.f;
}

// Per-point accumulation. MODE 0: fwd + Sp (18); 1: fwd + contracted Hessian (28); 2: fwd (16)
template <int MODE>
__device__ __forceinline__ void accum_point(
    float zx, float zy, float px, float py,
    float c20, float c21, float c22, float c23, float d0, float d1,
    float t10, float t11, float t12, float t13, float* acc) {
    float u0 = fmaf(c20, zx, fmaf(c21, zy, d0));
    float u1 = fmaf(c22, zx, fmaf(c23, zy, d1));
    float h0 = ftanh(u0), h1 = ftanh(u1);
    float s0 = fmaf(-h0, h0, 1.f), s1 = fmaf(-h1, h1, 1.f);
    float s0zx = s0 * zx, s0zy = s0 * zy;
    float s1zx = s1 * zx, s1zy = s1 * zy;
    acc[0]  = fmaf(px, h0, acc[0]);
    acc[1]  = fmaf(px, h1, acc[1]);
    acc[2]  = fmaf(py, h0, acc[2]);
    acc[3]  = fmaf(py, h1, acc[3]);
    acc[4]  = fmaf(px, s0, acc[4]);
    acc[5]  = fmaf(px, s1, acc[5]);
    acc[6]  = fmaf(py, s0, acc[6]);
    acc[7]  = fmaf(py, s1, acc[7]);
    acc[8]  = fmaf(px, s0zx, acc[8]);
    acc[9]  = fmaf(px, s0zy, acc[9]);
    acc[10] = fmaf(px, s1zx, acc[10]);
    acc[11] = fmaf(px, s1zy, acc[11]);
    acc[12] = fmaf(py, s0zx, acc[12]);
    acc[13] = fmaf(py, s0zy, acc[13]);
    acc[14] = fmaf(py, s1zx, acc[14]);
    acc[15] = fmaf(py, s1zy, acc[15]);
    if (MODE == 1) {
        float w0 = fmaf(t10, px, t12 * py);
        float w1 = fmaf(t11, px, t13 * py);
        float wh0 = w0 * (h0 * s0);
        float wh1 = w1 * (h1 * s1);
        acc[16] += wh0;
        acc[17] += wh1;
        float wh0zx = wh0 * zx, wh0zy = wh0 * zy;
        float wh1zx = wh1 * zx, wh1zy = wh1 * zy;
        acc[18] += wh0zx;
        acc[19] += wh0zy;
        acc[20] += wh1zx;
        acc[21] += wh1zy;
        acc[22] = fmaf(wh0zx, zx, acc[22]);
        acc[23] = fmaf(wh0zx, zy, acc[23]);
        acc[24] = fmaf(wh0zy, zy, acc[24]);
        acc[25] = fmaf(wh1zx, zx, acc[25]);
        acc[26] = fmaf(wh1zx, zy, acc[26]);
        acc[27] = fmaf(wh1zy, zy, acc[27]);
    }
    if (MODE == 0) {
        acc[16] += px;
        acc[17] += py;
    }
}

template <int MODE>
__global__ void __launch_bounds__(256, 4)
pass_kernel(const float* __restrict__ inp,
            const float* __restrict__ t1i, const float* __restrict__ b1i,
            const float* __restrict__ t2i, const float* __restrict__ b2i,
            const float* __restrict__ invK, const float* __restrict__ invKb,
            int K, int k) {
    constexpr int NACT = (MODE == 1) ? 28 : (MODE == 0 ? 18 : 16);
    __shared__ float sTh[12];
    __shared__ float sred[NACT];

    if (threadIdx.x == 0) {
        float th[12];
        if (k == 0) {
            th[0] = t1i[0]; th[1] = t1i[1]; th[2] = t1i[2]; th[3] = t1i[3];
            th[4] = b1i[0]; th[5] = b1i[1];
            th[6] = t2i[0]; th[7] = t2i[1]; th[8] = t2i[2]; th[9] = t2i[3];
            th[10] = b2i[0]; th[11] = b2i[1];
        } else {
            float pth[12], G[12];
#pragma unroll
            for (int j = 0; j < 12; ++j) pth[j] = gTheta[k - 1][j];
            compute_G(pth, gM[k - 1], gM[0][40], gM[0][41], invK, invKb,
                      0.5f / (float)K, G);
#pragma unroll
            for (int j = 0; j < 12; ++j) th[j] = pth[j] - LRATE * G[j];
        }
#pragma unroll
        for (int j = 0; j < 12; ++j) { sTh[j] = th[j]; gTheta[k][j] = th[j]; }
    }
    if (threadIdx.x < NACT) sred[threadIdx.x] = 0.f;
    __syncthreads();

    const float c20 = sTh[6], c21 = sTh[7], c22 = sTh[8], c23 = sTh[9];
    const float d0 = sTh[10], d1 = sTh[11];
    const float t10 = sTh[0], t11 = sTh[1], t12 = sTh[2], t13 = sTh[3];

    float acc[NACT];
#pragma unroll
    for (int j = 0; j < NACT; ++j) acc[j] = 0.f;

    const float4* q4 = (const float4*)inp;
    const float4* p4 = (const float4*)(inp + 2 * (size_t)K);
    const int npair = K >> 1;   // 2 points per float4
    const int stride = gridDim.x * blockDim.x;

    for (int t = blockIdx.x * blockDim.x + threadIdx.x; t < npair; t += stride) {
        float4 q = q4[t];
        float4 p = p4[t];
        accum_point<MODE>(q.x, q.y, p.x, p.y, c20, c21, c22, c23, d0, d1,
                          t10, t11, t12, t13, acc);
        accum_point<MODE>(q.z, q.w, p.z, p.w, c20, c21, c22, c23, d0, d1,
                          t10, t11, t12, t13, acc);
    }

    // scalar tail (odd K; dead for K = 2^20)
    if ((K & 1) && blockIdx.x == 0 && threadIdx.x == 0) {
        const float2* z2 = (const float2*)inp;
        float2 z = z2[K - 1], p2 = z2[2 * K - 1];
        accum_point<MODE>(z.x, z.y, p2.x, p2.y, c20, c21, c22, c23, d0, d1,
                          t10, t11, t12, t13, acc);
    }

#pragma unroll
    for (int j = 0; j < NACT; ++j) {
#pragma unroll
        for (int off = 16; off > 0; off >>= 1)
            acc[j] += __shfl_down_sync(0xffffffffu, acc[j], off);
    }
    if ((threadIdx.x & 31) == 0) {
#pragma unroll
        for (int j = 0; j < NACT; ++j) atomicAdd(&sred[j], acc[j]);
    }
    __syncthreads();
    if (threadIdx.x < NACT) {
        int g = (MODE == 0 && threadIdx.x >= 16) ? (40 + (int)threadIdx.x - 16)
                                                 : (int)threadIdx.x;
        atomicAdd(&gM[k][g], sred[threadIdx.x]);
    }
}

// ---------------- backward: 12-dim adjoint recursion (reads contracted T's) ------------
__global__ void backward_kernel(const float* __restrict__ invK,
                                const float* __restrict__ invKb, int K) {
    if (blockIdx.x != 0 || threadIdx.x != 0) return;
    const float inv2K = 0.5f / (float)K;
    float lam[12];
    compute_G(gTheta[NIT], gM[NIT], gM[0][40], gM[0][41], invK, invKb, inv2K, lam);
    for (int k = NIT - 1; k >= 0; --k) {
#pragma unroll
        for (int j = 0; j < 12; ++j) gLam[k][j] = lam[j];
        if (k > 0) {
            const float* M = gM[k];
            float y[12], t4[4], tb[2];
            sym4mv(invK, lam, t4);       y[0]=t4[0]; y[1]=t4[1]; y[2]=t4[2]; y[3]=t4[3];
            sym2mv(invKb, lam + 4, tb);  y[4]=tb[0]; y[5]=tb[1];
            sym4mv(invK, lam + 6, t4);   y[6]=t4[0]; y[7]=t4[1]; y[8]=t4[2]; y[9]=t4[3];
            sym2mv(invKb, lam + 10, tb); y[10]=tb[0]; y[11]=tb[1];

            const float* T4 = M + 16;   // [2]
            const float* T5 = M + 18;   // [2b+c]
            const float* T6 = M + 22;   // [3b + (c+e)]

            float PL[12];
#pragma unroll
            for (int a = 0; a < 2; ++a)
#pragma unroll
                for (int b = 0; b < 2; ++b)
                    PL[2 * a + b] = M[8 + 4 * a + 2 * b + 0] * lam[6 + 2 * b + 0]
                                  + M[8 + 4 * a + 2 * b + 1] * lam[6 + 2 * b + 1]
                                  + M[4 + 2 * a + b] * lam[10 + b];
            PL[4] = 0.f; PL[5] = 0.f;

#pragma unroll
            for (int b = 0; b < 2; ++b)
#pragma unroll
                for (int c = 0; c < 2; ++c) {
                    float v = lam[b] * M[8 + 2 * b + c] + lam[2 + b] * M[8 + 4 + 2 * b + c];
                    v -= 2.f * (T6[3 * b + c + 0] * lam[6 + 2 * b + 0] +
                                T6[3 * b + c + 1] * lam[6 + 2 * b + 1]);
                    v -= 2.f * T5[2 * b + c] * lam[10 + b];
                    PL[6 + 2 * b + c] = v;
                }
#pragma unroll
            for (int b = 0; b < 2; ++b) {
                float v = lam[b] * M[4 + b] + lam[2 + b] * M[4 + 2 + b];
                v -= 2.f * (T5[2 * b + 0] * lam[6 + 2 * b + 0] +
                            T5[2 * b + 1] * lam[6 + 2 * b + 1]);
                v -= 2.f * T4[b] * lam[10 + b];
                PL[10 + b] = v;
            }
#pragma unroll
            for (int j = 0; j < 12; ++j) lam[j] -= LRATE * (y[j] - inv2K * PL[j]);
        }
    }
}

// ---------------- phase C: dot_p reconstruction + advects, 2 pts/thread ----------------
__global__ void __launch_bounds__(256)
phasec_kernel(const float* __restrict__ inp, float* __restrict__ out, int K) {
    __shared__ float sTh[(NIT + 1) * 12];
    __shared__ float sLam[NIT * 12];
    for (int j = threadIdx.x; j < (NIT + 1) * 12; j += blockDim.x)
        sTh[j] = ((const float*)gTheta)[j];
    for (int j = threadIdx.x; j < NIT * 12; j += blockDim.x)
        sLam[j] = ((const float*)gLam)[j];
    __syncthreads();

    const int npair = K >> 1;
    const float inv2K = 0.5f / (float)K;
    int t = blockIdx.x * blockDim.x + threadIdx.x;

    if (t < npair) {
        const float4* q4 = (const float4*)inp;
        const float4* p4 = (const float4*)(inp + 2 * (size_t)K);
        const float4* x4 = (const float4*)(inp + 4 * (size_t)K);
        float4 qa = q4[t], pp = p4[t];
        float zx0 = qa.x, zy0 = qa.y, zx1 = qa.z, zy1 = qa.w;
        float px0 = pp.x, py0 = pp.y, px1 = pp.z, py1 = pp.w;
        float ax0 = 0.f, ay0 = 0.f, ax1 = 0.f, ay1 = 0.f;

#pragma unroll
        for (int kk = 0; kk < NIT; ++kk) {
            const float* th = &sTh[12 * kk];
            const float* L = &sLam[12 * kk];
            float a0 = th[0], a1 = th[1], a2 = th[2], a3 = th[3];
            float c0 = th[6], c1 = th[7], c2 = th[8], c3 = th[9];
            float d0 = th[10], d1 = th[11];
            float l0 = L[0], l1 = L[1], l2 = L[2], l3 = L[3];
            float q0 = L[6], q1 = L[7], q2 = L[8], q3 = L[9];
            float r0 = L[10], r1 = L[11];
            {
                float u0 = fmaf(c0, zx0, fmaf(c1, zy0, d0));
                float u1 = fmaf(c2, zx0, fmaf(c3, zy0, d1));
                float h0 = ftanh(u0), h1 = ftanh(u1);
                float s0 = fmaf(-h0, h0, 1.f), s1 = fmaf(-h1, h1, 1.f);
                float w0 = fmaf(a0, px0, a2 * py0);
                float w1 = fmaf(a1, px0, a3 * py0);
                float m0 = fmaf(l0, px0, l2 * py0);
                float m1 = fmaf(l1, px0, l3 * py0);
                float k0 = fmaf(q0, zx0, fmaf(q1, zy0, r0));
                float k1 = fmaf(q2, zx0, fmaf(q3, zy0, r1));
                float e0 = s0 * fmaf(-2.f * w0 * h0, k0, m0);
                float e1 = s1 * fmaf(-2.f * w1 * h1, k1, m1);
                float ws0 = w0 * s0, ws1 = w1 * s1;
                ax0 = fmaf(e0, c0, fmaf(e1, c2, fmaf(q0, ws0, fmaf(q2, ws1, ax0))));
                ay0 = fmaf(e0, c1, fmaf(e1, c3, fmaf(q1, ws0, fmaf(q3, ws1, ay0))));
            }
            {
                float u0 = fmaf(c0, zx1, fmaf(c1, zy1, d0));
                float u1 = fmaf(c2, zx1, fmaf(c3, zy1, d1));
                float h0 = ftanh(u0), h1 = ftanh(u1);
                float s0 = fmaf(-h0, h0, 1.f), s1 = fmaf(-h1, h1, 1.f);
                float w0 = fmaf(a0, px1, a2 * py1);
                float w1 = fmaf(a1, px1, a3 * py1);
                float m0 = fmaf(l0, px1, l2 * py1);
                float m1 = fmaf(l1, px1, l3 * py1);
                float k0 = fmaf(q0, zx1, fmaf(q1, zy1, r0));
                float k1 = fmaf(q2, zx1, fmaf(q3, zy1, r1));
                float e0 = s0 * fmaf(-2.f * w0 * h0, k0, m0);
                float e1 = s1 * fmaf(-2.f * w1 * h1, k1, m1);
                float ws0 = w0 * s0, ws1 = w1 * s1;
                ax1 = fmaf(e0, c0, fmaf(e1, c2, fmaf(q0, ws0, fmaf(q2, ws1, ax1))));
                ay1 = fmaf(e0, c1, fmaf(e1, c3, fmaf(q1, ws0, fmaf(q3, ws1, ay1))));
            }
        }

        const float* th = &sTh[12 * NIT];
        float a0 = th[0], a1 = th[1], a2 = th[2], a3 = th[3], b0 = th[4], b1v = th[5];
        float c0 = th[6], c1 = th[7], c2 = th[8], c3 = th[9], d0 = th[10], d1 = th[11];
        float4 xv = x4[t];
        float4 oq, op, ox;
        {
            float u0 = fmaf(c0, zx0, fmaf(c1, zy0, d0));
            float u1 = fmaf(c2, zx0, fmaf(c3, zy0, d1));
            float h0 = ftanh(u0), h1 = ftanh(u1);
            float s0 = fmaf(-h0, h0, 1.f), s1 = fmaf(-h1, h1, 1.f);
            float w0 = fmaf(a0, px0, a2 * py0);
            float w1 = fmaf(a1, px0, a3 * py0);
            float ws0 = w0 * s0, ws1 = w1 * s1;
            oq.x = fmaf(a0, h0, fmaf(a1, h1, b0));
            oq.y = fmaf(a2, h0, fmaf(a3, h1, b1v));
            op.x = inv2K * (LRATE * ax0 - (ws0 * c0 + ws1 * c2));
            op.y = inv2K * (LRATE * ay0 - (ws0 * c1 + ws1 * c3));
        }
        {
            float u0 = fmaf(c0, zx1, fmaf(c1, zy1, d0));
            float u1 = fmaf(c2, zx1, fmaf(c3, zy1, d1));
            float h0 = ftanh(u0), h1 = ftanh(u1);
            float s0 = fmaf(-h0, h0, 1.f), s1 = fmaf(-h1, h1, 1.f);
            float w0 = fmaf(a0, px1, a2 * py1);
            float w1 = fmaf(a1, px1, a3 * py1);
            float ws0 = w0 * s0, ws1 = w1 * s1;
            oq.z = fmaf(a0, h0, fmaf(a1, h1, b0));
            oq.w = fmaf(a2, h0, fmaf(a3, h1, b1v));
            op.z = inv2K * (LRATE * ax1 - (ws0 * c0 + ws1 * c2));
            op.w = inv2K * (LRATE * ay1 - (ws0 * c1 + ws1 * c3));
        }
        {
            float v0 = fmaf(c0, xv.x, fmaf(c1, xv.y, d0));
            float v1 = fmaf(c2, xv.x, fmaf(c3, xv.y, d1));
            float g0 = ftanh(v0), g1 = ftanh(v1);
            ox.x = fmaf(a0, g0, fmaf(a1, g1, b0));
            ox.y = fmaf(a2, g0, fmaf(a3, g1, b1v));
            float v2 = fmaf(c0, xv.z, fmaf(c1, xv.w, d0));
            float v3 = fmaf(c2, xv.z, fmaf(c3, xv.w, d1));
            float g2 = ftanh(v2), g3 = ftanh(v3);
            ox.z = fmaf(a0, g2, fmaf(a1, g3, b0));
            ox.w = fmaf(a2, g2, fmaf(a3, g3, b1v));
        }
        float4* o4 = (float4*)out;
        o4[t] = oq;
        o4[t + npair] = op;
        o4[t + 2 * npair] = ox;
    } else if ((K & 1) && t == npair) {
        const float2* z2 = (const float2*)inp;
        float2* o2 = (float2*)out;
        int i = K - 1;
        float zx = z2[i].x, zy = z2[i].y;
        float pxx = z2[K + i].x, pyy = z2[K + i].y;
        float axs = 0.f, ays = 0.f;
        for (int kk = 0; kk < NIT; ++kk) {
            const float* th = &sTh[12 * kk];
            const float* L = &sLam[12 * kk];
            float u0 = fmaf(th[6], zx, fmaf(th[7], zy, th[10]));
            float u1 = fmaf(th[8], zx, fmaf(th[9], zy, th[11]));
            float h0 = ftanh(u0), h1 = ftanh(u1);
            float s0 = fmaf(-h0, h0, 1.f), s1 = fmaf(-h1, h1, 1.f);
            float w0 = fmaf(th[0], pxx, th[2] * pyy);
            float w1 = fmaf(th[1], pxx, th[3] * pyy);
            float m0 = fmaf(L[0], pxx, L[2] * pyy);
            float m1 = fmaf(L[1], pxx, L[3] * pyy);
            float k0 = fmaf(L[6], zx, fmaf(L[7], zy, L[10]));
            float k1 = fmaf(L[8], zx, fmaf(L[9], zy, L[11]));
            float e0 = s0 * fmaf(-2.f * w0 * h0, k0, m0);
            float e1 = s1 * fmaf(-2.f * w1 * h1, k1, m1);
            float ws0 = w0 * s0, ws1 = w1 * s1;
            axs += e0 * th[6] + e1 * th[8] + L[6] * ws0 + L[8] * ws1;
            ays += e0 * th[7] + e1 * th[9] + L[7] * ws0 + L[9] * ws1;
        }
        const float* th = &sTh[12 * NIT];
        float u0 = fmaf(th[6], zx, fmaf(th[7], zy, th[10]));
        float u1 = fmaf(th[8], zx, fmaf(th[9], zy, th[11]));
        float h0 = ftanh(u0), h1 = ftanh(u1);
        float s0 = fmaf(-h0, h0, 1.f), s1 = fmaf(-h1, h1, 1.f);
        float w0 = fmaf(th[0], pxx, th[2] * pyy);
        float w1 = fmaf(th[1], pxx, th[3] * pyy);
        float ws0 = w0 * s0, ws1 = w1 * s1;
        o2[i] = make_float2(fmaf(th[0], h0, fmaf(th[1], h1, th[4])),
                            fmaf(th[2], h0, fmaf(th[3], h1, th[5])));
        o2[K + i] = make_float2(inv2K * (LRATE * axs - (ws0 * th[6] + ws1 * th[8])),
                                inv2K * (LRATE * ays - (ws0 * th[7] + ws1 * th[9])));
        float xxs = z2[2 * K + i].x, xys = z2[2 * K + i].y;
        float v0 = fmaf(th[6], xxs, fmaf(th[7], xys, th[10]));
        float v1 = fmaf(th[8], xxs, fmaf(th[9], xys, th[11]));
        float g0 = ftanh(v0), g1 = ftanh(v1);
        o2[2 * K + i] = make_float2(fmaf(th[0], g0, fmaf(th[1], g1, th[4])),
                                    fmaf(th[2], g0, fmaf(th[3], g1, th[5])));
    }
}

extern "C" void kernel_launch(void* const* d_in, const int* in_sizes, int n_in,
                              void* d_out, int out_size) {
    (void)n_in; (void)out_size;
    const float* inp   = (const float*)d_in[1];
    const float* t1i   = (const float*)d_in[2];
    const float* b1i   = (const float*)d_in[3];
    const float* t2i   = (const float*)d_in[4];
    const float* b2i   = (const float*)d_in[5];
    const float* invK  = (const float*)d_in[6];
    const float* invKb = (const float*)d_in[7];
    int K = in_sizes[1] / 6;

    zero_moments_kernel<<<1, 1024>>>();
    const int PB = 592;   // 4 blocks/SM * 148
    const int PT = 256;
    pass_kernel<0><<<PB, PT>>>(inp, t1i, b1i, t2i, b2i, invK, invKb, K, 0);
    for (int k = 1; k < NIT; ++k)
        pass_kernel<1><<<PB, PT>>>(inp, t1i, b1i, t2i, b2i, invK, invKb, K, k);
    pass_kernel<2><<<PB, PT>>>(inp, t1i, b1i, t2i, b2i, invK, invKb, K, NIT);
    backward_kernel<<<1, 1>>>(invK, invKb, K);
    int threads_needed = (K >> 1) + (K & 1);
    int blocks = (threads_needed + 255) / 256;
    phasec_kernel<<<blocks, 256>>>(inp, (float*)d_out, K);
}

// round 5
// speedup vs baseline: 1.3665x; 1.3665x over previous
#include <cuda_runtime.h>

#define LRATE 0.25f
#define NIT 20
#define MPAD 48

// Persistent device scratch (rewritten deterministically every launch)
__device__ float gM[NIT + 1][MPAD];      // per-iteration sums
__device__ float gTheta[NIT + 1][12];    // theta trajectory
__device__ float gLam[NIT][12];          // adjoints: gLam[k] = lambda_{k+1}

// theta layout [12]: t1 (0..3 row-major), b1 (4,5), t2 (6..9 row-major), b2 (10,11)
// gM layout:
//  0..3   M1_{ab} = sum p_a h_b
//  4..7   M2_{ab} = sum p_a s_b
//  8..15  M3_{abc}= sum p_a s_b z_c
// 16..17  T4_b    = sum w_b h_b s_b          (w_b = t1[0][b] px + t1[1][b] py at pass-k theta)
// 18..21  T5_bc   = sum w_b h_b s_b z_c
// 22..27  T6_b,(ce)= sum w_b h_b s_b z_c z_e (sym pair index c+e)
// 40..41  Sp_a    = sum p_a  (theta-independent; written by pass 0 only)

// tanh(x) = 1 - 2/(exp(2x)+1); exact at +/-inf via ex2/rcp saturation. 5 instructions.
__device__ __forceinline__ float ftanh(float x) {
    float e;
    asm("ex2.approx.f32 %0, %1;" : "=f"(e) : "f"(x * 2.8853900817779268f));
    float r;
    asm("rcp.approx.f32 %0, %1;" : "=f"(r) : "f"(e + 1.0f));
    return fmaf(-2.0f, r, 1.0f);
}

__device__ __forceinline__ void sym4mv(const float* __restrict__ A, const float* v, float* y) {
#pragma unroll
    for (int r = 0; r < 4; ++r) {
        float s = 0.f;
#pragma unroll
        for (int c = 0; c < 4; ++c) s += 0.5f * (A[4 * r + c] + A[4 * c + r]) * v[c];
        y[r] = s;
    }
}
__device__ __forceinline__ void sym2mv(const float* __restrict__ A, const float* v, float* y) {
#pragma unroll
    for (int r = 0; r < 2; ++r) {
        float s = 0.f;
#pragma unroll
        for (int c = 0; c < 2; ++c) s += 0.5f * (A[2 * r + c] + A[2 * c + r]) * v[c];
        y[r] = s;
    }
}

// G = dL/dtheta from forward moments (M[0..15]) + Sp
__device__ __forceinline__ void compute_G(const float* th, const float* M,
                                          float sp0, float sp1,
                                          const float* __restrict__ invK,
                                          const float* __restrict__ invKb,
                                          float inv2K, float* G) {
    float y[4], yb[2];
    sym4mv(invK, th, y);
#pragma unroll
    for (int r = 0; r < 4; ++r) G[r] = y[r] - inv2K * M[r];
    sym2mv(invKb, th + 4, yb);
    G[4] = yb[0] - inv2K * sp0;
    G[5] = yb[1] - inv2K * sp1;
    float v2[4] = {th[6] - 1.f, th[7], th[8], th[9] - 1.f};
    sym4mv(invK, v2, y);
#pragma unroll
    for (int b = 0; b < 2; ++b)
#pragma unroll
        for (int c = 0; c < 2; ++c) {
            float pot = th[b] * M[8 + 2 * b + c] + th[2 + b] * M[8 + 4 + 2 * b + c];
            G[6 + 2 * b + c] = y[2 * b + c] - inv2K * pot;
        }
    sym2mv(invKb, th + 10, yb);
#pragma unroll
    for (int b = 0; b < 2; ++b) {
        float pot = th[b] * M[4 + b] + th[2 + b] * M[4 + 2 + b];
        G[10 + b] = yb[b] - inv2K * pot;
    }
}

__global__ void zero_moments_kernel() {
    int t = threadIdx.x;
    if (t < (NIT + 1) * MPAD) ((float*)gM)[t] = 0.f;
}

// Per-point accumulation. MODE 0: fwd + Sp (18); 1: fwd + contracted Hessian (28); 2: fwd (16)
template <int MODE>
__device__ __forceinline__ void accum_point(
    float zx, float zy, float px, float py,
    float c20, float c21, float c22, float c23, float d0, float d1,
    float t10, float t11, float t12, float t13, float* acc) {
    float u0 = fmaf(c20, zx, fmaf(c21, zy, d0));
    float u1 = fmaf(c22, zx, fmaf(c23, zy, d1));
    float h0 = ftanh(u0), h1 = ftanh(u1);
    float s0 = fmaf(-h0, h0, 1.f), s1 = fmaf(-h1, h1, 1.f);
    float s0zx = s0 * zx, s0zy = s0 * zy;
    float s1zx = s1 * zx, s1zy = s1 * zy;
    acc[0]  = fmaf(px, h0, acc[0]);
    acc[1]  = fmaf(px, h1, acc[1]);
    acc[2]  = fmaf(py, h0, acc[2]);
    acc[3]  = fmaf(py, h1, acc[3]);
    acc[4]  = fmaf(px, s0, acc[4]);
    acc[5]  = fmaf(px, s1, acc[5]);
    acc[6]  = fmaf(py, s0, acc[6]);
    acc[7]  = fmaf(py, s1, acc[7]);
    acc[8]  = fmaf(px, s0zx, acc[8]);
    acc[9]  = fmaf(px, s0zy, acc[9]);
    acc[10] = fmaf(px, s1zx, acc[10]);
    acc[11] = fmaf(px, s1zy, acc[11]);
    acc[12] = fmaf(py, s0zx, acc[12]);
    acc[13] = fmaf(py, s0zy, acc[13]);
    acc[14] = fmaf(py, s1zx, acc[14]);
    acc[15] = fmaf(py, s1zy, acc[15]);
    if (MODE == 1) {
        float w0 = fmaf(t10, px, t12 * py);
        float w1 = fmaf(t11, px, t13 * py);
        float wh0 = w0 * (h0 * s0);
        float wh1 = w1 * (h1 * s1);
        acc[16] += wh0;
        acc[17] += wh1;
        float wh0zx = wh0 * zx, wh0zy = wh0 * zy;
        float wh1zx = wh1 * zx, wh1zy = wh1 * zy;
        acc[18] += wh0zx;
        acc[19] += wh0zy;
        acc[20] += wh1zx;
        acc[21] += wh1zy;
        acc[22] = fmaf(wh0zx, zx, acc[22]);
        acc[23] = fmaf(wh0zx, zy, acc[23]);
        acc[24] = fmaf(wh0zy, zy, acc[24]);
        acc[25] = fmaf(wh1zx, zx, acc[25]);
        acc[26] = fmaf(wh1zx, zy, acc[26]);
        acc[27] = fmaf(wh1zy, zy, acc[27]);
    }
    if (MODE == 0) {
        acc[16] += px;
        acc[17] += py;
    }
}

template <int MODE>
__global__ void __launch_bounds__(256, 3)
pass_kernel(const float* __restrict__ inp,
            const float* __restrict__ t1i, const float* __restrict__ b1i,
            const float* __restrict__ t2i, const float* __restrict__ b2i,
            const float* __restrict__ invK, const float* __restrict__ invKb,
            int K, int k) {
    constexpr int NACT = (MODE == 1) ? 28 : (MODE == 0 ? 18 : 16);
    constexpr int STR = NACT + 1;   // padded stride: gcd(STR,32)=1 -> conflict-free STS
    __shared__ float sTh[12];
    __shared__ float sred[NACT];
    __shared__ float sAcc[256 * STR];

    if (threadIdx.x == 0) {
        float th[12];
        if (k == 0) {
            th[0] = t1i[0]; th[1] = t1i[1]; th[2] = t1i[2]; th[3] = t1i[3];
            th[4] = b1i[0]; th[5] = b1i[1];
            th[6] = t2i[0]; th[7] = t2i[1]; th[8] = t2i[2]; th[9] = t2i[3];
            th[10] = b2i[0]; th[11] = b2i[1];
        } else {
            float pth[12], G[12];
#pragma unroll
            for (int j = 0; j < 12; ++j) pth[j] = gTheta[k - 1][j];
            compute_G(pth, gM[k - 1], gM[0][40], gM[0][41], invK, invKb,
                      0.5f / (float)K, G);
#pragma unroll
            for (int j = 0; j < 12; ++j) th[j] = pth[j] - LRATE * G[j];
        }
#pragma unroll
        for (int j = 0; j < 12; ++j) { sTh[j] = th[j]; gTheta[k][j] = th[j]; }
    }
    if (threadIdx.x < NACT) sred[threadIdx.x] = 0.f;
    __syncthreads();

    const float c20 = sTh[6], c21 = sTh[7], c22 = sTh[8], c23 = sTh[9];
    const float d0 = sTh[10], d1 = sTh[11];
    const float t10 = sTh[0], t11 = sTh[1], t12 = sTh[2], t13 = sTh[3];

    float acc[NACT];
#pragma unroll
    for (int j = 0; j < NACT; ++j) acc[j] = 0.f;

    const float4* q4 = (const float4*)inp;
    const float4* p4 = (const float4*)(inp + 2 * (size_t)K);
    const int npair = K >> 1;   // 2 points per float4
    const int stride = gridDim.x * blockDim.x;

    for (int t = blockIdx.x * blockDim.x + threadIdx.x; t < npair; t += stride) {
        float4 q = q4[t];
        float4 p = p4[t];
        accum_point<MODE>(q.x, q.y, p.x, p.y, c20, c21, c22, c23, d0, d1,
                          t10, t11, t12, t13, acc);
        accum_point<MODE>(q.z, q.w, p.z, p.w, c20, c21, c22, c23, d0, d1,
                          t10, t11, t12, t13, acc);
    }

    // scalar tail (odd K; dead for K = 2^20)
    if ((K & 1) && blockIdx.x == 0 && threadIdx.x == 0) {
        const float2* z2 = (const float2*)inp;
        float2 z = z2[K - 1], p2 = z2[2 * K - 1];
        accum_point<MODE>(z.x, z.y, p2.x, p2.y, c20, c21, c22, c23, d0, d1,
                          t10, t11, t12, t13, acc);
    }

    // ---- smem transpose reduction (no warp shuffles) ----
#pragma unroll
    for (int j = 0; j < NACT; ++j) sAcc[threadIdx.x * STR + j] = acc[j];
    __syncthreads();
    {
        int w = threadIdx.x >> 5;
        int lane = threadIdx.x & 31;
        if (lane < NACT) {
            float s = 0.f;
            int base = (w << 5) * STR + lane;
#pragma unroll
            for (int i = 0; i < 32; ++i) s += sAcc[base + i * STR];
            atomicAdd(&sred[lane], s);
        }
    }
    __syncthreads();
    if (threadIdx.x < NACT) {
        int g = (MODE == 0 && threadIdx.x >= 16) ? (40 + (int)threadIdx.x - 16)
                                                 : (int)threadIdx.x;
        atomicAdd(&gM[k][g], sred[threadIdx.x]);
    }
}

// ---------------- backward: 12-dim adjoint recursion (reads contracted T's) ------------
__global__ void backward_kernel(const float* __restrict__ invK,
                                const float* __restrict__ invKb, int K) {
    if (blockIdx.x != 0 || threadIdx.x != 0) return;
    const float inv2K = 0.5f / (float)K;
    float lam[12];
    compute_G(gTheta[NIT], gM[NIT], gM[0][40], gM[0][41], invK, invKb, inv2K, lam);
    for (int k = NIT - 1; k >= 0; --k) {
#pragma unroll
        for (int j = 0; j < 12; ++j) gLam[k][j] = lam[j];
        if (k > 0) {
            const float* M = gM[k];
            float y[12], t4[4], tb[2];
            sym4mv(invK, lam, t4);       y[0]=t4[0]; y[1]=t4[1]; y[2]=t4[2]; y[3]=t4[3];
            sym2mv(invKb, lam + 4, tb);  y[4]=tb[0]; y[5]=tb[1];
            sym4mv(invK, lam + 6, t4);   y[6]=t4[0]; y[7]=t4[1]; y[8]=t4[2]; y[9]=t4[3];
            sym2mv(invKb, lam + 10, tb); y[10]=tb[0]; y[11]=tb[1];

            const float* T4 = M + 16;   // [2]
            const float* T5 = M + 18;   // [2b+c]
            const float* T6 = M + 22;   // [3b + (c+e)]

            float PL[12];
#pragma unroll
            for (int a = 0; a < 2; ++a)
#pragma unroll
                for (int b = 0; b < 2; ++b)
                    PL[2 * a + b] = M[8 + 4 * a + 2 * b + 0] * lam[6 + 2 * b + 0]
                                  + M[8 + 4 * a + 2 * b + 1] * lam[6 + 2 * b + 1]
                                  + M[4 + 2 * a + b] * lam[10 + b];
            PL[4] = 0.f; PL[5] = 0.f;

#pragma unroll
            for (int b = 0; b < 2; ++b)
#pragma unroll
                for (int c = 0; c < 2; ++c) {
                    float v = lam[b] * M[8 + 2 * b + c] + lam[2 + b] * M[8 + 4 + 2 * b + c];
                    v -= 2.f * (T6[3 * b + c + 0] * lam[6 + 2 * b + 0] +
                                T6[3 * b + c + 1] * lam[6 + 2 * b + 1]);
                    v -= 2.f * T5[2 * b + c] * lam[10 + b];
                    PL[6 + 2 * b + c] = v;
                }
#pragma unroll
            for (int b = 0; b < 2; ++b) {
                float v = lam[b] * M[4 + b] + lam[2 + b] * M[4 + 2 + b];
                v -= 2.f * (T5[2 * b + 0] * lam[6 + 2 * b + 0] +
                            T5[2 * b + 1] * lam[6 + 2 * b + 1]);
                v -= 2.f * T4[b] * lam[10 + b];
                PL[10 + b] = v;
            }
#pragma unroll
            for (int j = 0; j < 12; ++j) lam[j] -= LRATE * (y[j] - inv2K * PL[j]);
        }
    }
}

// ---------------- phase C: dot_p reconstruction + advects, 2 pts/thread ----------------
__global__ void __launch_bounds__(256)
phasec_kernel(const float* __restrict__ inp, float* __restrict__ out, int K) {
    __shared__ float sTh[(NIT + 1) * 12];
    __shared__ float sLam[NIT * 12];
    for (int j = threadIdx.x; j < (NIT + 1) * 12; j += blockDim.x)
        sTh[j] = ((const float*)gTheta)[j];
    for (int j = threadIdx.x; j < NIT * 12; j += blockDim.x)
        sLam[j] = ((const float*)gLam)[j];
    __syncthreads();

    const int npair = K >> 1;
    const float inv2K = 0.5f / (float)K;
    int t = blockIdx.x * blockDim.x + threadIdx.x;

    if (t < npair) {
        const float4* q4 = (const float4*)inp;
        const float4* p4 = (const float4*)(inp + 2 * (size_t)K);
        const float4* x4 = (const float4*)(inp + 4 * (size_t)K);
        float4 qa = q4[t], pp = p4[t];
        float zx0 = qa.x, zy0 = qa.y, zx1 = qa.z, zy1 = qa.w;
        float px0 = pp.x, py0 = pp.y, px1 = pp.z, py1 = pp.w;
        float ax0 = 0.f, ay0 = 0.f, ax1 = 0.f, ay1 = 0.f;

#pragma unroll
        for (int kk = 0; kk < NIT; ++kk) {
            const float* th = &sTh[12 * kk];
            const float* L = &sLam[12 * kk];
            float a0 = th[0], a1 = th[1], a2 = th[2], a3 = th[3];
            float c0 = th[6], c1 = th[7], c2 = th[8], c3 = th[9];
            float d0 = th[10], d1 = th[11];
            float l0 = L[0], l1 = L[1], l2 = L[2], l3 = L[3];
            float q0 = L[6], q1 = L[7], q2 = L[8], q3 = L[9];
            float r0 = L[10], r1 = L[11];
            {
                float u0 = fmaf(c0, zx0, fmaf(c1, zy0, d0));
                float u1 = fmaf(c2, zx0, fmaf(c3, zy0, d1));
                float h0 = ftanh(u0), h1 = ftanh(u1);
                float s0 = fmaf(-h0, h0, 1.f), s1 = fmaf(-h1, h1, 1.f);
                float w0 = fmaf(a0, px0, a2 * py0);
                float w1 = fmaf(a1, px0, a3 * py0);
                float m0 = fmaf(l0, px0, l2 * py0);
                float m1 = fmaf(l1, px0, l3 * py0);
                float k0 = fmaf(q0, zx0, fmaf(q1, zy0, r0));
                float k1 = fmaf(q2, zx0, fmaf(q3, zy0, r1));
                float e0 = s0 * fmaf(-2.f * w0 * h0, k0, m0);
                float e1 = s1 * fmaf(-2.f * w1 * h1, k1, m1);
                float ws0 = w0 * s0, ws1 = w1 * s1;
                ax0 = fmaf(e0, c0, fmaf(e1, c2, fmaf(q0, ws0, fmaf(q2, ws1, ax0))));
                ay0 = fmaf(e0, c1, fmaf(e1, c3, fmaf(q1, ws0, fmaf(q3, ws1, ay0))));
            }
            {
                float u0 = fmaf(c0, zx1, fmaf(c1, zy1, d0));
                float u1 = fmaf(c2, zx1, fmaf(c3, zy1, d1));
                float h0 = ftanh(u0), h1 = ftanh(u1);
                float s0 = fmaf(-h0, h0, 1.f), s1 = fmaf(-h1, h1, 1.f);
                float w0 = fmaf(a0, px1, a2 * py1);
                float w1 = fmaf(a1, px1, a3 * py1);
                float m0 = fmaf(l0, px1, l2 * py1);
                float m1 = fmaf(l1, px1, l3 * py1);
                float k0 = fmaf(q0, zx1, fmaf(q1, zy1, r0));
                float k1 = fmaf(q2, zx1, fmaf(q3, zy1, r1));
                float e0 = s0 * fmaf(-2.f * w0 * h0, k0, m0);
                float e1 = s1 * fmaf(-2.f * w1 * h1, k1, m1);
                float ws0 = w0 * s0, ws1 = w1 * s1;
                ax1 = fmaf(e0, c0, fmaf(e1, c2, fmaf(q0, ws0, fmaf(q2, ws1, ax1))));
                ay1 = fmaf(e0, c1, fmaf(e1, c3, fmaf(q1, ws0, fmaf(q3, ws1, ay1))));
            }
        }

        const float* th = &sTh[12 * NIT];
        float a0 = th[0], a1 = th[1], a2 = th[2], a3 = th[3], b0 = th[4], b1v = th[5];
        float c0 = th[6], c1 = th[7], c2 = th[8], c3 = th[9], d0 = th[10], d1 = th[11];
        float4 xv = x4[t];
        float4 oq, op, ox;
        {
            float u0 = fmaf(c0, zx0, fmaf(c1, zy0, d0));
            float u1 = fmaf(c2, zx0, fmaf(c3, zy0, d1));
            float h0 = ftanh(u0), h1 = ftanh(u1);
            float s0 = fmaf(-h0, h0, 1.f), s1 = fmaf(-h1, h1, 1.f);
            float w0 = fmaf(a0, px0, a2 * py0);
            float w1 = fmaf(a1, px0, a3 * py0);
            float ws0 = w0 * s0, ws1 = w1 * s1;
            oq.x = fmaf(a0, h0, fmaf(a1, h1, b0));
            oq.y = fmaf(a2, h0, fmaf(a3, h1, b1v));
            op.x = inv2K * (LRATE * ax0 - (ws0 * c0 + ws1 * c2));
            op.y = inv2K * (LRATE * ay0 - (ws0 * c1 + ws1 * c3));
        }
        {
            float u0 = fmaf(c0, zx1, fmaf(c1, zy1, d0));
            float u1 = fmaf(c2, zx1, fmaf(c3, zy1, d1));
            float h0 = ftanh(u0), h1 = ftanh(u1);
            float s0 = fmaf(-h0, h0, 1.f), s1 = fmaf(-h1, h1, 1.f);
            float w0 = fmaf(a0, px1, a2 * py1);
            float w1 = fmaf(a1, px1, a3 * py1);
            float ws0 = w0 * s0, ws1 = w1 * s1;
            oq.z = fmaf(a0, h0, fmaf(a1, h1, b0));
            oq.w = fmaf(a2, h0, fmaf(a3, h1, b1v));
            op.z = inv2K * (LRATE * ax1 - (ws0 * c0 + ws1 * c2));
            op.w = inv2K * (LRATE * ay1 - (ws0 * c1 + ws1 * c3));
        }
        {
            float v0 = fmaf(c0, xv.x, fmaf(c1, xv.y, d0));
            float v1 = fmaf(c2, xv.x, fmaf(c3, xv.y, d1));
            float g0 = ftanh(v0), g1 = ftanh(v1);
            ox.x = fmaf(a0, g0, fmaf(a1, g1, b0));
            ox.y = fmaf(a2, g0, fmaf(a3, g1, b1v));
            float v2 = fmaf(c0, xv.z, fmaf(c1, xv.w, d0));
            float v3 = fmaf(c2, xv.z, fmaf(c3, xv.w, d1));
            float g2 = ftanh(v2), g3 = ftanh(v3);
            ox.z = fmaf(a0, g2, fmaf(a1, g3, b0));
            ox.w = fmaf(a2, g2, fmaf(a3, g3, b1v));
        }
        float4* o4 = (float4*)out;
        o4[t] = oq;
        o4[t + npair] = op;
        o4[t + 2 * npair] = ox;
    } else if ((K & 1) && t == npair) {
        const float2* z2 = (const float2*)inp;
        float2* o2 = (float2*)out;
        int i = K - 1;
        float zx = z2[i].x, zy = z2[i].y;
        float pxx = z2[K + i].x, pyy = z2[K + i].y;
        float axs = 0.f, ays = 0.f;
        for (int kk = 0; kk < NIT; ++kk) {
            const float* th = &sTh[12 * kk];
            const float* L = &sLam[12 * kk];
            float u0 = fmaf(th[6], zx, fmaf(th[7], zy, th[10]));
            float u1 = fmaf(th[8], zx, fmaf(th[9], zy, th[11]));
            float h0 = ftanh(u0), h1 = ftanh(u1);
            float s0 = fmaf(-h0, h0, 1.f), s1 = fmaf(-h1, h1, 1.f);
            float w0 = fmaf(th[0], pxx, th[2] * pyy);
            float w1 = fmaf(th[1], pxx, th[3] * pyy);
            float m0 = fmaf(L[0], pxx, L[2] * pyy);
            float m1 = fmaf(L[1], pxx, L[3] * pyy);
            float k0 = fmaf(L[6], zx, fmaf(L[7], zy, L[10]));
            float k1 = fmaf(L[8], zx, fmaf(L[9], zy, L[11]));
            float e0 = s0 * fmaf(-2.f * w0 * h0, k0, m0);
            float e1 = s1 * fmaf(-2.f * w1 * h1, k1, m1);
            float ws0 = w0 * s0, ws1 = w1 * s1;
            axs += e0 * th[6] + e1 * th[8] + L[6] * ws0 + L[8] * ws1;
            ays += e0 * th[7] + e1 * th[9] + L[7] * ws0 + L[9] * ws1;
        }
        const float* th = &sTh[12 * NIT];
        float u0 = fmaf(th[6], zx, fmaf(th[7], zy, th[10]));
        float u1 = fmaf(th[8], zx, fmaf(th[9], zy, th[11]));
        float h0 = ftanh(u0), h1 = ftanh(u1);
        float s0 = fmaf(-h0, h0, 1.f), s1 = fmaf(-h1, h1, 1.f);
        float w0 = fmaf(th[0], pxx, th[2] * pyy);
        float w1 = fmaf(th[1], pxx, th[3] * pyy);
        float ws0 = w0 * s0, ws1 = w1 * s1;
        o2[i] = make_float2(fmaf(th[0], h0, fmaf(th[1], h1, th[4])),
                            fmaf(th[2], h0, fmaf(th[3], h1, th[5])));
        o2[K + i] = make_float2(inv2K * (LRATE * axs - (ws0 * th[6] + ws1 * th[8])),
                                inv2K * (LRATE * ays - (ws0 * th[7] + ws1 * th[9])));
        float xxs = z2[2 * K + i].x, xys = z2[2 * K + i].y;
        float v0 = fmaf(th[6], xxs, fmaf(th[7], xys, th[10]));
        float v1 = fmaf(th[8], xxs, fmaf(th[9], xys, th[11]));
        float g0 = ftanh(v0), g1 = ftanh(v1);
        o2[2 * K + i] = make_float2(fmaf(th[0], g0, fmaf(th[1], g1, th[4])),
                                    fmaf(th[2], g0, fmaf(th[3], g1, th[5])));
    }
}

extern "C" void kernel_launch(void* const* d_in, const int* in_sizes, int n_in,
                              void* d_out, int out_size) {
    (void)n_in; (void)out_size;
    const float* inp   = (const float*)d_in[1];
    const float* t1i   = (const float*)d_in[2];
    const float* b1i   = (const float*)d_in[3];
    const float* t2i   = (const float*)d_in[4];
    const float* b2i   = (const float*)d_in[5];
    const float* invK  = (const float*)d_in[6];
    const float* invKb = (const float*)d_in[7];
    int K = in_sizes[1] / 6;

    zero_moments_kernel<<<1, 1024>>>();
    const int PB = 444;   // 3 blocks/SM * 148
    const int PT = 256;
    pass_kernel<0><<<PB, PT>>>(inp, t1i, b1i, t2i, b2i, invK, invKb, K, 0);
    for (int k = 1; k < NIT; ++k)
        pass_kernel<1><<<PB, PT>>>(inp, t1i, b1i, t2i, b2i, invK, invKb, K, k);
    pass_kernel<2><<<PB, PT>>>(inp, t1i, b1i, t2i, b2i, invK, invKb, K, NIT);
    backward_kernel<<<1, 1>>>(invK, invKb, K);
    int threads_needed = (K >> 1) + (K & 1);
    int blocks = (threads_needed + 255) / 256;
    phasec_kernel<<<blocks, 256>>>(inp, (float*)d_out, K);
}

// round 6
// speedup vs baseline: 1.4794x; 1.0826x over previous
#include <cuda_runtime.h>

#define LRATE 0.25f
#define NIT 20
#define MPAD 48
#define NBLK 296
#define NTHR 256
#define NPT 7   // float4 (=2 points) per thread => 14 points/thread

// Persistent device scratch (rewritten deterministically every launch)
__device__ float gM[NIT + 1][MPAD];
__device__ float gTheta[NIT + 1][12];
__device__ float gLam[NIT][12];
__device__ unsigned int gBar;

// tanh(x) = 1 - 2/(exp(2x)+1); 5 instructions, exact at +/-inf.
__device__ __forceinline__ float ftanh(float x) {
    float e;
    asm("ex2.approx.f32 %0, %1;" : "=f"(e) : "f"(x * 2.8853900817779268f));
    float r;
    asm("rcp.approx.f32 %0, %1;" : "=f"(r) : "f"(e + 1.0f));
    return fmaf(-2.0f, r, 1.0f);
}

__device__ __forceinline__ void sym4mv(const float* __restrict__ A, const float* v, float* y) {
#pragma unroll
    for (int r = 0; r < 4; ++r) {
        float s = 0.f;
#pragma unroll
        for (int c = 0; c < 4; ++c) s += 0.5f * (A[4 * r + c] + A[4 * c + r]) * v[c];
        y[r] = s;
    }
}
__device__ __forceinline__ void sym2mv(const float* __restrict__ A, const float* v, float* y) {
#pragma unroll
    for (int r = 0; r < 2; ++r) {
        float s = 0.f;
#pragma unroll
        for (int c = 0; c < 2; ++c) s += 0.5f * (A[2 * r + c] + A[2 * c + r]) * v[c];
        y[r] = s;
    }
}

__device__ __forceinline__ void compute_G(const float* th, const float* M,
                                          float sp0, float sp1,
                                          const float* __restrict__ invK,
                                          const float* __restrict__ invKb,
                                          float inv2K, float* G) {
    float y[4], yb[2];
    sym4mv(invK, th, y);
#pragma unroll
    for (int r = 0; r < 4; ++r) G[r] = y[r] - inv2K * M[r];
    sym2mv(invKb, th + 4, yb);
    G[4] = yb[0] - inv2K * sp0;
    G[5] = yb[1] - inv2K * sp1;
    float v2[4] = {th[6] - 1.f, th[7], th[8], th[9] - 1.f};
    sym4mv(invK, v2, y);
#pragma unroll
    for (int b = 0; b < 2; ++b)
#pragma unroll
        for (int c = 0; c < 2; ++c) {
            float pot = th[b] * M[8 + 2 * b + c] + th[2 + b] * M[8 + 4 + 2 * b + c];
            G[6 + 2 * b + c] = y[2 * b + c] - inv2K * pot;
        }
    sym2mv(invKb, th + 10, yb);
#pragma unroll
    for (int b = 0; b < 2; ++b) {
        float pot = th[b] * M[4 + b] + th[2 + b] * M[4 + 2 + b];
        G[10 + b] = yb[b] - inv2K * pot;
    }
}

__global__ void zero_kernel() {
    int t = threadIdx.x;
    if (t < (NIT + 1) * MPAD) ((float*)gM)[t] = 0.f;
    if (t == 1023) gBar = 0u;
}

// Software grid barrier: monotonic counter, release-arrive + acquire-spin.
// Safe: all NBLK blocks are co-resident (2 blocks/SM * >=148 SMs, enforced by launch bounds).
__device__ __forceinline__ void grid_barrier(unsigned int target) {
    __syncthreads();
    if (threadIdx.x == 0) {
        asm volatile("red.release.gpu.global.add.u32 [%0], 1;" :: "l"(&gBar) : "memory");
        unsigned int v;
        do {
            asm volatile("ld.acquire.gpu.global.u32 %0, [%1];" : "=r"(v) : "l"(&gBar) : "memory");
        } while (v < target);
    }
    __syncthreads();
}

// Accumulate one point into the 28 per-pass sums (16 fwd moments + 12 contracted Hessian T's)
__device__ __forceinline__ void accum_pt(
    float zx, float zy, float px, float py,
    float c20, float c21, float c22, float c23, float d0, float d1,
    float t10, float t11, float t12, float t13, float* acc) {
    float u0 = fmaf(c20, zx, fmaf(c21, zy, d0));
    float u1 = fmaf(c22, zx, fmaf(c23, zy, d1));
    float h0 = ftanh(u0), h1 = ftanh(u1);
    float s0 = fmaf(-h0, h0, 1.f), s1 = fmaf(-h1, h1, 1.f);
    float s0zx = s0 * zx, s0zy = s0 * zy;
    float s1zx = s1 * zx, s1zy = s1 * zy;
    acc[0]  = fmaf(px, h0, acc[0]);
    acc[1]  = fmaf(px, h1, acc[1]);
    acc[2]  = fmaf(py, h0, acc[2]);
    acc[3]  = fmaf(py, h1, acc[3]);
    acc[4]  = fmaf(px, s0, acc[4]);
    acc[5]  = fmaf(px, s1, acc[5]);
    acc[6]  = fmaf(py, s0, acc[6]);
    acc[7]  = fmaf(py, s1, acc[7]);
    acc[8]  = fmaf(px, s0zx, acc[8]);
    acc[9]  = fmaf(px, s0zy, acc[9]);
    acc[10] = fmaf(px, s1zx, acc[10]);
    acc[11] = fmaf(px, s1zy, acc[11]);
    acc[12] = fmaf(py, s0zx, acc[12]);
    acc[13] = fmaf(py, s0zy, acc[13]);
    acc[14] = fmaf(py, s1zx, acc[14]);
    acc[15] = fmaf(py, s1zy, acc[15]);
    float w0 = fmaf(t10, px, t12 * py);
    float w1 = fmaf(t11, px, t13 * py);
    float wh0 = w0 * (h0 * s0);
    float wh1 = w1 * (h1 * s1);
    acc[16] += wh0;
    acc[17] += wh1;
    float wh0zx = wh0 * zx, wh0zy = wh0 * zy;
    float wh1zx = wh1 * zx, wh1zy = wh1 * zy;
    acc[18] += wh0zx;
    acc[19] += wh0zy;
    acc[20] += wh1zx;
    acc[21] += wh1zy;
    acc[22] = fmaf(wh0zx, zx, acc[22]);
    acc[23] = fmaf(wh0zx, zy, acc[23]);
    acc[24] = fmaf(wh0zy, zy, acc[24]);
    acc[25] = fmaf(wh1zx, zx, acc[25]);
    acc[26] = fmaf(wh1zx, zy, acc[26]);
    acc[27] = fmaf(wh1zy, zy, acc[27]);
}

// One fused kernel: load q,p into registers once; run all 21 passes with grid
// barriers between them; block 0 finishes with the 12-dim adjoint recursion.
__global__ void __launch_bounds__(NTHR, 2)
mega_kernel(const float* __restrict__ inp,
            const float* __restrict__ t1i, const float* __restrict__ b1i,
            const float* __restrict__ t2i, const float* __restrict__ b2i,
            const float* __restrict__ invK, const float* __restrict__ invKb,
            int K) {
    __shared__ float sThAll[(NIT + 1) * 12];
    __shared__ float sred[28];
    __shared__ float sAcc[NTHR * 29];

    const int gtid = blockIdx.x * NTHR + threadIdx.x;
    const int npair = K >> 1;
    const float4* q4 = (const float4*)inp;
    const float4* p4 = (const float4*)(inp + 2 * (size_t)K);
    const float inv2K = 0.5f / (float)K;

    // ---- load this thread's 14 points into registers (zero-padded) ----
    float4 qr[NPT], pr[NPT];
    float sp0 = 0.f, sp1 = 0.f;
#pragma unroll
    for (int i = 0; i < NPT; ++i) {
        int idx = gtid + i * (NBLK * NTHR);
        if (idx < npair) { qr[i] = q4[idx]; pr[i] = p4[idx]; }
        else { qr[i] = make_float4(0.f, 0.f, 0.f, 0.f); pr[i] = qr[i]; }
        sp0 += pr[i].x + pr[i].z;
        sp1 += pr[i].y + pr[i].w;
    }
    // Sp (theta-independent): reduce once, straight to gM[0][40..41]
#pragma unroll
    for (int off = 16; off > 0; off >>= 1) {
        sp0 += __shfl_down_sync(0xffffffffu, sp0, off);
        sp1 += __shfl_down_sync(0xffffffffu, sp1, off);
    }
    if ((threadIdx.x & 31) == 0) {
        atomicAdd(&gM[0][40], sp0);
        atomicAdd(&gM[0][41], sp1);
    }

    // ---- 21 passes ----
    for (int k = 0; k <= NIT; ++k) {
        if (threadIdx.x == 0) {
            float th[12];
            if (k == 0) {
                th[0] = t1i[0]; th[1] = t1i[1]; th[2] = t1i[2]; th[3] = t1i[3];
                th[4] = b1i[0]; th[5] = b1i[1];
                th[6] = t2i[0]; th[7] = t2i[1]; th[8] = t2i[2]; th[9] = t2i[3];
                th[10] = b2i[0]; th[11] = b2i[1];
            } else {
                float G[12];
                compute_G(&sThAll[12 * (k - 1)], gM[k - 1], gM[0][40], gM[0][41],
                          invK, invKb, inv2K, G);
#pragma unroll
                for (int j = 0; j < 12; ++j) th[j] = sThAll[12 * (k - 1) + j] - LRATE * G[j];
            }
#pragma unroll
            for (int j = 0; j < 12; ++j) {
                sThAll[12 * k + j] = th[j];
                if (blockIdx.x == 0) gTheta[k][j] = th[j];
            }
        }
        if (threadIdx.x < 28) sred[threadIdx.x] = 0.f;
        __syncthreads();

        const float t10 = sThAll[12 * k + 0], t11 = sThAll[12 * k + 1];
        const float t12 = sThAll[12 * k + 2], t13 = sThAll[12 * k + 3];
        const float c20 = sThAll[12 * k + 6], c21 = sThAll[12 * k + 7];
        const float c22 = sThAll[12 * k + 8], c23 = sThAll[12 * k + 9];
        const float d0 = sThAll[12 * k + 10], d1 = sThAll[12 * k + 11];

        float acc[28];
#pragma unroll
        for (int j = 0; j < 28; ++j) acc[j] = 0.f;
#pragma unroll
        for (int i = 0; i < NPT; ++i) {
            accum_pt(qr[i].x, qr[i].y, pr[i].x, pr[i].y,
                     c20, c21, c22, c23, d0, d1, t10, t11, t12, t13, acc);
            accum_pt(qr[i].z, qr[i].w, pr[i].z, pr[i].w,
                     c20, c21, c22, c23, d0, d1, t10, t11, t12, t13, acc);
        }

        // smem transpose reduction (stride 29, conflict-free)
#pragma unroll
        for (int j = 0; j < 28; ++j) sAcc[threadIdx.x * 29 + j] = acc[j];
        __syncthreads();
        {
            int w = threadIdx.x >> 5;
            int lane = threadIdx.x & 31;
            if (lane < 28) {
                float s = 0.f;
                int base = (w << 5) * 29 + lane;
#pragma unroll
                for (int i = 0; i < 32; ++i) s += sAcc[base + i * 29];
                atomicAdd(&sred[lane], s);
            }
        }
        __syncthreads();
        if (threadIdx.x < 28) atomicAdd(&gM[k][threadIdx.x], sred[threadIdx.x]);

        grid_barrier((unsigned)NBLK * (unsigned)(k + 1));
    }

    // ---- backward (block 0, thread 0): lambda recursion from stored sums ----
    if (blockIdx.x == 0 && threadIdx.x == 0) {
        float lam[12];
        compute_G(&sThAll[12 * NIT], gM[NIT], gM[0][40], gM[0][41], invK, invKb, inv2K, lam);
        for (int k = NIT - 1; k >= 0; --k) {
#pragma unroll
            for (int j = 0; j < 12; ++j) gLam[k][j] = lam[j];
            if (k > 0) {
                const float* M = gM[k];
                float y[12], t4[4], tb[2];
                sym4mv(invK, lam, t4);       y[0]=t4[0]; y[1]=t4[1]; y[2]=t4[2]; y[3]=t4[3];
                sym2mv(invKb, lam + 4, tb);  y[4]=tb[0]; y[5]=tb[1];
                sym4mv(invK, lam + 6, t4);   y[6]=t4[0]; y[7]=t4[1]; y[8]=t4[2]; y[9]=t4[3];
                sym2mv(invKb, lam + 10, tb); y[10]=tb[0]; y[11]=tb[1];

                const float* T4 = M + 16;
                const float* T5 = M + 18;
                const float* T6 = M + 22;

                float PL[12];
#pragma unroll
                for (int a = 0; a < 2; ++a)
#pragma unroll
                    for (int b = 0; b < 2; ++b)
                        PL[2 * a + b] = M[8 + 4 * a + 2 * b + 0] * lam[6 + 2 * b + 0]
                                      + M[8 + 4 * a + 2 * b + 1] * lam[6 + 2 * b + 1]
                                      + M[4 + 2 * a + b] * lam[10 + b];
                PL[4] = 0.f; PL[5] = 0.f;
#pragma unroll
                for (int b = 0; b < 2; ++b)
#pragma unroll
                    for (int c = 0; c < 2; ++c) {
                        float v = lam[b] * M[8 + 2 * b + c] + lam[2 + b] * M[8 + 4 + 2 * b + c];
                        v -= 2.f * (T6[3 * b + c + 0] * lam[6 + 2 * b + 0] +
                                    T6[3 * b + c + 1] * lam[6 + 2 * b + 1]);
                        v -= 2.f * T5[2 * b + c] * lam[10 + b];
                        PL[6 + 2 * b + c] = v;
                    }
#pragma unroll
                for (int b = 0; b < 2; ++b) {
                    float v = lam[b] * M[4 + b] + lam[2 + b] * M[4 + 2 + b];
                    v -= 2.f * (T5[2 * b + 0] * lam[6 + 2 * b + 0] +
                                T5[2 * b + 1] * lam[6 + 2 * b + 1]);
                    v -= 2.f * T4[b] * lam[10 + b];
                    PL[10 + b] = v;
                }
#pragma unroll
                for (int j = 0; j < 12; ++j) lam[j] -= LRATE * (y[j] - inv2K * PL[j]);
            }
        }
    }
}

// ---------------- phase C: dot_p reconstruction + advects, 2 pts/thread ----------------
__global__ void __launch_bounds__(256)
phasec_kernel(const float* __restrict__ inp, float* __restrict__ out, int K) {
    __shared__ float sTh[(NIT + 1) * 12];
    __shared__ float sLam[NIT * 12];
    for (int j = threadIdx.x; j < (NIT + 1) * 12; j += blockDim.x)
        sTh[j] = ((const float*)gTheta)[j];
    for (int j = threadIdx.x; j < NIT * 12; j += blockDim.x)
        sLam[j] = ((const float*)gLam)[j];
    __syncthreads();

    const int npair = K >> 1;
    const float inv2K = 0.5f / (float)K;
    int t = blockIdx.x * blockDim.x + threadIdx.x;

    if (t < npair) {
        const float4* q4 = (const float4*)inp;
        const float4* p4 = (const float4*)(inp + 2 * (size_t)K);
        const float4* x4 = (const float4*)(inp + 4 * (size_t)K);
        float4 qa = q4[t], pp = p4[t];
        float zx0 = qa.x, zy0 = qa.y, zx1 = qa.z, zy1 = qa.w;
        float px0 = pp.x, py0 = pp.y, px1 = pp.z, py1 = pp.w;
        float ax0 = 0.f, ay0 = 0.f, ax1 = 0.f, ay1 = 0.f;

#pragma unroll
        for (int kk = 0; kk < NIT; ++kk) {
            const float* th = &sTh[12 * kk];
            const float* L = &sLam[12 * kk];
            float a0 = th[0], a1 = th[1], a2 = th[2], a3 = th[3];
            float c0 = th[6], c1 = th[7], c2 = th[8], c3 = th[9];
            float d0 = th[10], d1 = th[11];
            float l0 = L[0], l1 = L[1], l2 = L[2], l3 = L[3];
            float q0 = L[6], q1 = L[7], q2 = L[8], q3 = L[9];
            float r0 = L[10], r1 = L[11];
            {
                float u0 = fmaf(c0, zx0, fmaf(c1, zy0, d0));
                float u1 = fmaf(c2, zx0, fmaf(c3, zy0, d1));
                float h0 = ftanh(u0), h1 = ftanh(u1);
                float s0 = fmaf(-h0, h0, 1.f), s1 = fmaf(-h1, h1, 1.f);
                float w0 = fmaf(a0, px0, a2 * py0);
                float w1 = fmaf(a1, px0, a3 * py0);
                float m0 = fmaf(l0, px0, l2 * py0);
                float m1 = fmaf(l1, px0, l3 * py0);
                float k0 = fmaf(q0, zx0, fmaf(q1, zy0, r0));
                float k1 = fmaf(q2, zx0, fmaf(q3, zy0, r1));
                float e0 = s0 * fmaf(-2.f * w0 * h0, k0, m0);
                float e1 = s1 * fmaf(-2.f * w1 * h1, k1, m1);
                float ws0 = w0 * s0, ws1 = w1 * s1;
                ax0 = fmaf(e0, c0, fmaf(e1, c2, fmaf(q0, ws0, fmaf(q2, ws1, ax0))));
                ay0 = fmaf(e0, c1, fmaf(e1, c3, fmaf(q1, ws0, fmaf(q3, ws1, ay0))));
            }
            {
                float u0 = fmaf(c0, zx1, fmaf(c1, zy1, d0));
                float u1 = fmaf(c2, zx1, fmaf(c3, zy1, d1));
                float h0 = ftanh(u0), h1 = ftanh(u1);
                float s0 = fmaf(-h0, h0, 1.f), s1 = fmaf(-h1, h1, 1.f);
                float w0 = fmaf(a0, px1, a2 * py1);
                float w1 = fmaf(a1, px1, a3 * py1);
                float m0 = fmaf(l0, px1, l2 * py1);
                float m1 = fmaf(l1, px1, l3 * py1);
                float k0 = fmaf(q0, zx1, fmaf(q1, zy1, r0));
                float k1 = fmaf(q2, zx1, fmaf(q3, zy1, r1));
                float e0 = s0 * fmaf(-2.f * w0 * h0, k0, m0);
                float e1 = s1 * fmaf(-2.f * w1 * h1, k1, m1);
                float ws0 = w0 * s0, ws1 = w1 * s1;
                ax1 = fmaf(e0, c0, fmaf(e1, c2, fmaf(q0, ws0, fmaf(q2, ws1, ax1))));
                ay1 = fmaf(e0, c1, fmaf(e1, c3, fmaf(q1, ws0, fmaf(q3, ws1, ay1))));
            }
        }

        const float* th = &sTh[12 * NIT];
        float a0 = th[0], a1 = th[1], a2 = th[2], a3 = th[3], b0 = th[4], b1v = th[5];
        float c0 = th[6], c1 = th[7], c2 = th[8], c3 = th[9], d0 = th[10], d1 = th[11];
        float4 xv = x4[t];
        float4 oq, op, ox;
        {
            float u0 = fmaf(c0, zx0, fmaf(c1, zy0, d0));
            float u1 = fmaf(c2, zx0, fmaf(c3, zy0, d1));
            float h0 = ftanh(u0), h1 = ftanh(u1);
            float s0 = fmaf(-h0, h0, 1.f), s1 = fmaf(-h1, h1, 1.f);
            float w0 = fmaf(a0, px0, a2 * py0);
            float w1 = fmaf(a1, px0, a3 * py0);
            float ws0 = w0 * s0, ws1 = w1 * s1;
            oq.x = fmaf(a0, h0, fmaf(a1, h1, b0));
            oq.y = fmaf(a2, h0, fmaf(a3, h1, b1v));
            op.x = inv2K * (LRATE * ax0 - (ws0 * c0 + ws1 * c2));
            op.y = inv2K * (LRATE * ay0 - (ws0 * c1 + ws1 * c3));
        }
        {
            float u0 = fmaf(c0, zx1, fmaf(c1, zy1, d0));
            float u1 = fmaf(c2, zx1, fmaf(c3, zy1, d1));
            float h0 = ftanh(u0), h1 = ftanh(u1);
            float s0 = fmaf(-h0, h0, 1.f), s1 = fmaf(-h1, h1, 1.f);
            float w0 = fmaf(a0, px1, a2 * py1);
            float w1 = fmaf(a1, px1, a3 * py1);
            float ws0 = w0 * s0, ws1 = w1 * s1;
            oq.z = fmaf(a0, h0, fmaf(a1, h1, b0));
            oq.w = fmaf(a2, h0, fmaf(a3, h1, b1v));
            op.z = inv2K * (LRATE * ax1 - (ws0 * c0 + ws1 * c2));
            op.w = inv2K * (LRATE * ay1 - (ws0 * c1 + ws1 * c3));
        }
        {
            float v0 = fmaf(c0, xv.x, fmaf(c1, xv.y, d0));
            float v1 = fmaf(c2, xv.x, fmaf(c3, xv.y, d1));
            float g0 = ftanh(v0), g1 = ftanh(v1);
            ox.x = fmaf(a0, g0, fmaf(a1, g1, b0));
            ox.y = fmaf(a2, g0, fmaf(a3, g1, b1v));
            float v2 = fmaf(c0, xv.z, fmaf(c1, xv.w, d0));
            float v3 = fmaf(c2, xv.z, fmaf(c3, xv.w, d1));
            float g2 = ftanh(v2), g3 = ftanh(v3);
            ox.z = fmaf(a0, g2, fmaf(a1, g3, b0));
            ox.w = fmaf(a2, g2, fmaf(a3, g3, b1v));
        }
        float4* o4 = (float4*)out;
        o4[t] = oq;
        o4[t + npair] = op;
        o4[t + 2 * npair] = ox;
    }
}

extern "C" void kernel_launch(void* const* d_in, const int* in_sizes, int n_in,
                              void* d_out, int out_size) {
    (void)n_in; (void)out_size;
    const float* inp   = (const float*)d_in[1];
    const float* t1i   = (const float*)d_in[2];
    const float* b1i   = (const float*)d_in[3];
    const float* t2i   = (const float*)d_in[4];
    const float* b2i   = (const float*)d_in[5];
    const float* invK  = (const float*)d_in[6];
    const float* invKb = (const float*)d_in[7];
    int K = in_sizes[1] / 6;

    zero_kernel<<<1, 1024>>>();
    mega_kernel<<<NBLK, NTHR>>>(inp, t1i, b1i, t2i, b2i, invK, invKb, K);
    int blocks = ((K >> 1) + 255) / 256;
    phasec_kernel<<<blocks, 256>>>(inp, (float*)d_out, K);
}

// round 7
// speedup vs baseline: 1.6641x; 1.1249x over previous
#include <cuda_runtime.h>

#define LRATE 0.25f
#define NIT 20
#define MPAD 48
#define NBLK 296
#define NTHR 256
#define NPT 7   // float4 (=2 points) per thread => 14 points/thread

// Persistent device scratch (rewritten deterministically every launch)
__device__ float gM[NIT + 1][MPAD];
__device__ float gTheta[NIT + 1][12];
__device__ float gLam[NIT][12];
__device__ unsigned int gBar;

// single-instruction HW tanh (sm_75+); max rel err ~5e-4, fine vs 1e-3 gate
__device__ __forceinline__ float ftanh(float x) {
    float r;
    asm("tanh.approx.f32 %0, %1;" : "=f"(r) : "f"(x));
    return r;
}

__device__ __forceinline__ void sym4mv(const float* __restrict__ A, const float* v, float* y) {
#pragma unroll
    for (int r = 0; r < 4; ++r) {
        float s = 0.f;
#pragma unroll
        for (int c = 0; c < 4; ++c) s += 0.5f * (A[4 * r + c] + A[4 * c + r]) * v[c];
        y[r] = s;
    }
}
__device__ __forceinline__ void sym2mv(const float* __restrict__ A, const float* v, float* y) {
#pragma unroll
    for (int r = 0; r < 2; ++r) {
        float s = 0.f;
#pragma unroll
        for (int c = 0; c < 2; ++c) s += 0.5f * (A[2 * r + c] + A[2 * c + r]) * v[c];
        y[r] = s;
    }
}

__device__ __forceinline__ void compute_G(const float* th, const float* M,
                                          float sp0, float sp1,
                                          const float* __restrict__ invK,
                                          const float* __restrict__ invKb,
                                          float inv2K, float* G) {
    float y[4], yb[2];
    sym4mv(invK, th, y);
#pragma unroll
    for (int r = 0; r < 4; ++r) G[r] = y[r] - inv2K * M[r];
    sym2mv(invKb, th + 4, yb);
    G[4] = yb[0] - inv2K * sp0;
    G[5] = yb[1] - inv2K * sp1;
    float v2[4] = {th[6] - 1.f, th[7], th[8], th[9] - 1.f};
    sym4mv(invK, v2, y);
#pragma unroll
    for (int b = 0; b < 2; ++b)
#pragma unroll
        for (int c = 0; c < 2; ++c) {
            float pot = th[b] * M[8 + 2 * b + c] + th[2 + b] * M[8 + 4 + 2 * b + c];
            G[6 + 2 * b + c] = y[2 * b + c] - inv2K * pot;
        }
    sym2mv(invKb, th + 10, yb);
#pragma unroll
    for (int b = 0; b < 2; ++b) {
        float pot = th[b] * M[4 + b] + th[2 + b] * M[4 + 2 + b];
        G[10 + b] = yb[b] - inv2K * pot;
    }
}

__global__ void zero_kernel() {
    int t = threadIdx.x;
    if (t < (NIT + 1) * MPAD) ((float*)gM)[t] = 0.f;
    if (t == 1023) gBar = 0u;
}

// Software grid barrier (all NBLK blocks co-resident: 2 blocks/SM * >=148 SMs)
__device__ __forceinline__ void grid_barrier(unsigned int target) {
    __syncthreads();
    if (threadIdx.x == 0) {
        asm volatile("red.release.gpu.global.add.u32 [%0], 1;" :: "l"(&gBar) : "memory");
        unsigned int v;
        do {
            asm volatile("ld.acquire.gpu.global.u32 %0, [%1];" : "=r"(v) : "l"(&gBar) : "memory");
        } while (v < target);
    }
    __syncthreads();
}

// Accumulate one point into the 28 per-pass sums
__device__ __forceinline__ void accum_pt(
    float zx, float zy, float px, float py,
    float c20, float c21, float c22, float c23, float d0, float d1,
    float t10, float t11, float t12, float t13, float* acc) {
    float u0 = fmaf(c20, zx, fmaf(c21, zy, d0));
    float u1 = fmaf(c22, zx, fmaf(c23, zy, d1));
    float h0 = ftanh(u0), h1 = ftanh(u1);
    float s0 = fmaf(-h0, h0, 1.f), s1 = fmaf(-h1, h1, 1.f);
    float s0zx = s0 * zx, s0zy = s0 * zy;
    float s1zx = s1 * zx, s1zy = s1 * zy;
    acc[0]  = fmaf(px, h0, acc[0]);
    acc[1]  = fmaf(px, h1, acc[1]);
    acc[2]  = fmaf(py, h0, acc[2]);
    acc[3]  = fmaf(py, h1, acc[3]);
    acc[4]  = fmaf(px, s0, acc[4]);
    acc[5]  = fmaf(px, s1, acc[5]);
    acc[6]  = fmaf(py, s0, acc[6]);
    acc[7]  = fmaf(py, s1, acc[7]);
    acc[8]  = fmaf(px, s0zx, acc[8]);
    acc[9]  = fmaf(px, s0zy, acc[9]);
    acc[10] = fmaf(px, s1zx, acc[10]);
    acc[11] = fmaf(px, s1zy, acc[11]);
    acc[12] = fmaf(py, s0zx, acc[12]);
    acc[13] = fmaf(py, s0zy, acc[13]);
    acc[14] = fmaf(py, s1zx, acc[14]);
    acc[15] = fmaf(py, s1zy, acc[15]);
    float w0 = fmaf(t10, px, t12 * py);
    float w1 = fmaf(t11, px, t13 * py);
    float wh0 = w0 * (h0 * s0);
    float wh1 = w1 * (h1 * s1);
    acc[16] += wh0;
    acc[17] += wh1;
    float wh0zx = wh0 * zx, wh0zy = wh0 * zy;
    float wh1zx = wh1 * zx, wh1zy = wh1 * zy;
    acc[18] += wh0zx;
    acc[19] += wh0zy;
    acc[20] += wh1zx;
    acc[21] += wh1zy;
    acc[22] = fmaf(wh0zx, zx, acc[22]);
    acc[23] = fmaf(wh0zx, zy, acc[23]);
    acc[24] = fmaf(wh0zy, zy, acc[24]);
    acc[25] = fmaf(wh1zx, zx, acc[25]);
    acc[26] = fmaf(wh1zx, zy, acc[26]);
    acc[27] = fmaf(wh1zy, zy, acc[27]);
}

// Fully fused: load q,p once into registers; 21 passes with grid barriers;
// block 0 runs the adjoint recursion; then every block computes final outputs
// for its own register-resident points.
__global__ void __launch_bounds__(NTHR, 2)
mega_kernel(const float* __restrict__ inp,
            const float* __restrict__ t1i, const float* __restrict__ b1i,
            const float* __restrict__ t2i, const float* __restrict__ b2i,
            const float* __restrict__ invK, const float* __restrict__ invKb,
            float* __restrict__ out, int K) {
    __shared__ float sThAll[(NIT + 1) * 12];
    __shared__ float sLam[NIT * 12];
    __shared__ float sred[28];
    __shared__ float sAcc[NTHR * 29];

    const int gtid = blockIdx.x * NTHR + threadIdx.x;
    const int npair = K >> 1;
    const float4* q4 = (const float4*)inp;
    const float4* p4 = (const float4*)(inp + 2 * (size_t)K);
    const float4* x4 = (const float4*)(inp + 4 * (size_t)K);
    const float inv2K = 0.5f / (float)K;

    // ---- load this thread's 14 points into registers (zero-padded) ----
    float4 qr[NPT], pr[NPT];
    float sp0 = 0.f, sp1 = 0.f;
#pragma unroll
    for (int i = 0; i < NPT; ++i) {
        int idx = gtid + i * (NBLK * NTHR);
        if (idx < npair) { qr[i] = q4[idx]; pr[i] = p4[idx]; }
        else { qr[i] = make_float4(0.f, 0.f, 0.f, 0.f); pr[i] = qr[i]; }
        sp0 += pr[i].x + pr[i].z;
        sp1 += pr[i].y + pr[i].w;
    }
#pragma unroll
    for (int off = 16; off > 0; off >>= 1) {
        sp0 += __shfl_down_sync(0xffffffffu, sp0, off);
        sp1 += __shfl_down_sync(0xffffffffu, sp1, off);
    }
    if ((threadIdx.x & 31) == 0) {
        atomicAdd(&gM[0][40], sp0);
        atomicAdd(&gM[0][41], sp1);
    }

    // ---- 21 passes ----
    for (int k = 0; k <= NIT; ++k) {
        if (threadIdx.x == 0) {
            float th[12];
            if (k == 0) {
                th[0] = t1i[0]; th[1] = t1i[1]; th[2] = t1i[2]; th[3] = t1i[3];
                th[4] = b1i[0]; th[5] = b1i[1];
                th[6] = t2i[0]; th[7] = t2i[1]; th[8] = t2i[2]; th[9] = t2i[3];
                th[10] = b2i[0]; th[11] = b2i[1];
            } else {
                float G[12];
                compute_G(&sThAll[12 * (k - 1)], gM[k - 1], gM[0][40], gM[0][41],
                          invK, invKb, inv2K, G);
#pragma unroll
                for (int j = 0; j < 12; ++j) th[j] = sThAll[12 * (k - 1) + j] - LRATE * G[j];
            }
#pragma unroll
            for (int j = 0; j < 12; ++j) sThAll[12 * k + j] = th[j];
        }
        if (threadIdx.x < 28) sred[threadIdx.x] = 0.f;
        __syncthreads();

        const float t10 = sThAll[12 * k + 0], t11 = sThAll[12 * k + 1];
        const float t12 = sThAll[12 * k + 2], t13 = sThAll[12 * k + 3];
        const float c20 = sThAll[12 * k + 6], c21 = sThAll[12 * k + 7];
        const float c22 = sThAll[12 * k + 8], c23 = sThAll[12 * k + 9];
        const float d0 = sThAll[12 * k + 10], d1 = sThAll[12 * k + 11];

        float acc[28];
#pragma unroll
        for (int j = 0; j < 28; ++j) acc[j] = 0.f;
#pragma unroll
        for (int i = 0; i < NPT; ++i) {
            accum_pt(qr[i].x, qr[i].y, pr[i].x, pr[i].y,
                     c20, c21, c22, c23, d0, d1, t10, t11, t12, t13, acc);
            accum_pt(qr[i].z, qr[i].w, pr[i].z, pr[i].w,
                     c20, c21, c22, c23, d0, d1, t10, t11, t12, t13, acc);
        }

        // smem transpose reduction (stride 29, conflict-free)
#pragma unroll
        for (int j = 0; j < 28; ++j) sAcc[threadIdx.x * 29 + j] = acc[j];
        __syncthreads();
        {
            int w = threadIdx.x >> 5;
            int lane = threadIdx.x & 31;
            if (lane < 28) {
                float s = 0.f;
                int base = (w << 5) * 29 + lane;
#pragma unroll
                for (int i = 0; i < 32; ++i) s += sAcc[base + i * 29];
                atomicAdd(&sred[lane], s);
            }
        }
        __syncthreads();
        if (threadIdx.x < 28) atomicAdd(&gM[k][threadIdx.x], sred[threadIdx.x]);

        grid_barrier((unsigned)NBLK * (unsigned)(k + 1));
    }

    // ---- backward (block 0, thread 0) ----
    if (blockIdx.x == 0 && threadIdx.x == 0) {
        float lam[12];
        compute_G(&sThAll[12 * NIT], gM[NIT], gM[0][40], gM[0][41], invK, invKb, inv2K, lam);
        for (int k = NIT - 1; k >= 0; --k) {
#pragma unroll
            for (int j = 0; j < 12; ++j) gLam[k][j] = lam[j];
            if (k > 0) {
                const float* M = gM[k];
                float y[12], t4[4], tb[2];
                sym4mv(invK, lam, t4);       y[0]=t4[0]; y[1]=t4[1]; y[2]=t4[2]; y[3]=t4[3];
                sym2mv(invKb, lam + 4, tb);  y[4]=tb[0]; y[5]=tb[1];
                sym4mv(invK, lam + 6, t4);   y[6]=t4[0]; y[7]=t4[1]; y[8]=t4[2]; y[9]=t4[3];
                sym2mv(invKb, lam + 10, tb); y[10]=tb[0]; y[11]=tb[1];

                const float* T4 = M + 16;
                const float* T5 = M + 18;
                const float* T6 = M + 22;

                float PL[12];
#pragma unroll
                for (int a = 0; a < 2; ++a)
#pragma unroll
                    for (int b = 0; b < 2; ++b)
                        PL[2 * a + b] = M[8 + 4 * a + 2 * b + 0] * lam[6 + 2 * b + 0]
                                      + M[8 + 4 * a + 2 * b + 1] * lam[6 + 2 * b + 1]
                                      + M[4 + 2 * a + b] * lam[10 + b];
                PL[4] = 0.f; PL[5] = 0.f;
#pragma unroll
                for (int b = 0; b < 2; ++b)
#pragma unroll
                    for (int c = 0; c < 2; ++c) {
                        float v = lam[b] * M[8 + 2 * b + c] + lam[2 + b] * M[8 + 4 + 2 * b + c];
                        v -= 2.f * (T6[3 * b + c + 0] * lam[6 + 2 * b + 0] +
                                    T6[3 * b + c + 1] * lam[6 + 2 * b + 1]);
                        v -= 2.f * T5[2 * b + c] * lam[10 + b];
                        PL[6 + 2 * b + c] = v;
                    }
#pragma unroll
                for (int b = 0; b < 2; ++b) {
                    float v = lam[b] * M[4 + b] + lam[2 + b] * M[4 + 2 + b];
                    v -= 2.f * (T5[2 * b + 0] * lam[6 + 2 * b + 0] +
                                T5[2 * b + 1] * lam[6 + 2 * b + 1]);
                    v -= 2.f * T4[b] * lam[10 + b];
                    PL[10 + b] = v;
                }
#pragma unroll
                for (int j = 0; j < 12; ++j) lam[j] -= LRATE * (y[j] - inv2K * PL[j]);
            }
        }
    }

    grid_barrier((unsigned)NBLK * (unsigned)(NIT + 2));

    // ---- phase C (fused): outputs for this thread's register-resident points ----
    for (int j = threadIdx.x; j < NIT * 12; j += NTHR)
        sLam[j] = ((const float*)gLam)[j];
    __syncthreads();

    float4* o4 = (float4*)out;
#pragma unroll
    for (int i = 0; i < NPT; ++i) {
        int idx = gtid + i * (NBLK * NTHR);
        if (idx >= npair) break;
        float zx0 = qr[i].x, zy0 = qr[i].y, zx1 = qr[i].z, zy1 = qr[i].w;
        float px0 = pr[i].x, py0 = pr[i].y, px1 = pr[i].z, py1 = pr[i].w;
        float ax0 = 0.f, ay0 = 0.f, ax1 = 0.f, ay1 = 0.f;

        for (int kk = 0; kk < NIT; ++kk) {
            const float* th = &sThAll[12 * kk];
            const float* L = &sLam[12 * kk];
            float a0 = th[0], a1 = th[1], a2 = th[2], a3 = th[3];
            float c0 = th[6], c1 = th[7], c2 = th[8], c3 = th[9];
            float d0 = th[10], d1 = th[11];
            float l0 = L[0], l1 = L[1], l2 = L[2], l3 = L[3];
            float q0 = L[6], q1 = L[7], q2 = L[8], q3 = L[9];
            float r0 = L[10], r1 = L[11];
            {
                float u0 = fmaf(c0, zx0, fmaf(c1, zy0, d0));
                float u1 = fmaf(c2, zx0, fmaf(c3, zy0, d1));
                float h0 = ftanh(u0), h1 = ftanh(u1);
                float s0 = fmaf(-h0, h0, 1.f), s1 = fmaf(-h1, h1, 1.f);
                float w0 = fmaf(a0, px0, a2 * py0);
                float w1 = fmaf(a1, px0, a3 * py0);
                float m0 = fmaf(l0, px0, l2 * py0);
                float m1 = fmaf(l1, px0, l3 * py0);
                float k0 = fmaf(q0, zx0, fmaf(q1, zy0, r0));
                float k1 = fmaf(q2, zx0, fmaf(q3, zy0, r1));
                float e0 = s0 * fmaf(-2.f * w0 * h0, k0, m0);
                float e1 = s1 * fmaf(-2.f * w1 * h1, k1, m1);
                float ws0 = w0 * s0, ws1 = w1 * s1;
                ax0 = fmaf(e0, c0, fmaf(e1, c2, fmaf(q0, ws0, fmaf(q2, ws1, ax0))));
                ay0 = fmaf(e0, c1, fmaf(e1, c3, fmaf(q1, ws0, fmaf(q3, ws1, ay0))));
            }
            {
                float u0 = fmaf(c0, zx1, fmaf(c1, zy1, d0));
                float u1 = fmaf(c2, zx1, fmaf(c3, zy1, d1));
                float h0 = ftanh(u0), h1 = ftanh(u1);
                float s0 = fmaf(-h0, h0, 1.f), s1 = fmaf(-h1, h1, 1.f);
                float w0 = fmaf(a0, px1, a2 * py1);
                float w1 = fmaf(a1, px1, a3 * py1);
                float m0 = fmaf(l0, px1, l2 * py1);
                float m1 = fmaf(l1, px1, l3 * py1);
                float k0 = fmaf(q0, zx1, fmaf(q1, zy1, r0));
                float k1 = fmaf(q2, zx1, fmaf(q3, zy1, r1));
                float e0 = s0 * fmaf(-2.f * w0 * h0, k0, m0);
                float e1 = s1 * fmaf(-2.f * w1 * h1, k1, m1);
                float ws0 = w0 * s0, ws1 = w1 * s1;
                ax1 = fmaf(e0, c0, fmaf(e1, c2, fmaf(q0, ws0, fmaf(q2, ws1, ax1))));
                ay1 = fmaf(e0, c1, fmaf(e1, c3, fmaf(q1, ws0, fmaf(q3, ws1, ay1))));
            }
        }

        const float* th = &sThAll[12 * NIT];
        float a0 = th[0], a1 = th[1], a2 = th[2], a3 = th[3], b0 = th[4], b1v = th[5];
        float c0 = th[6], c1 = th[7], c2 = th[8], c3 = th[9], d0 = th[10], d1 = th[11];
        float4 xv = x4[idx];
        float4 oq, op, ox;
        {
            float u0 = fmaf(c0, zx0, fmaf(c1, zy0, d0));
            float u1 = fmaf(c2, zx0, fmaf(c3, zy0, d1));
            float h0 = ftanh(u0), h1 = ftanh(u1);
            float s0 = fmaf(-h0, h0, 1.f), s1 = fmaf(-h1, h1, 1.f);
            float w0 = fmaf(a0, px0, a2 * py0);
            float w1 = fmaf(a1, px0, a3 * py0);
            float ws0 = w0 * s0, ws1 = w1 * s1;
            oq.x = fmaf(a0, h0, fmaf(a1, h1, b0));
            oq.y = fmaf(a2, h0, fmaf(a3, h1, b1v));
            op.x = inv2K * (LRATE * ax0 - (ws0 * c0 + ws1 * c2));
            op.y = inv2K * (LRATE * ay0 - (ws0 * c1 + ws1 * c3));
        }
        {
            float u0 = fmaf(c0, zx1, fmaf(c1, zy1, d0));
            float u1 = fmaf(c2, zx1, fmaf(c3, zy1, d1));
            float h0 = ftanh(u0), h1 = ftanh(u1);
            float s0 = fmaf(-h0, h0, 1.f), s1 = fmaf(-h1, h1, 1.f);
            float w0 = fmaf(a0, px1, a2 * py1);
            float w1 = fmaf(a1, px1, a3 * py1);
            float ws0 = w0 * s0, ws1 = w1 * s1;
            oq.z = fmaf(a0, h0, fmaf(a1, h1, b0));
            oq.w = fmaf(a2, h0, fmaf(a3, h1, b1v));
            op.z = inv2K * (LRATE * ax1 - (ws0 * c0 + ws1 * c2));
            op.w = inv2K * (LRATE * ay1 - (ws0 * c1 + ws1 * c3));
        }
        {
            float v0 = fmaf(c0, xv.x, fmaf(c1, xv.y, d0));
            float v1 = fmaf(c2, xv.x, fmaf(c3, xv.y, d1));
            float g0 = ftanh(v0), g1 = ftanh(v1);
            ox.x = fmaf(a0, g0, fmaf(a1, g1, b0));
            ox.y = fmaf(a2, g0, fmaf(a3, g1, b1v));
            float v2 = fmaf(c0, xv.z, fmaf(c1, xv.w, d0));
            float v3 = fmaf(c2, xv.z, fmaf(c3, xv.w, d1));
            float g2 = ftanh(v2), g3 = ftanh(v3);
            ox.z = fmaf(a0, g2, fmaf(a1, g3, b0));
            ox.w = fmaf(a2, g2, fmaf(a3, g3, b1v));
        }
        o4[idx] = oq;
        o4[idx + npair] = op;
        o4[idx + 2 * npair] = ox;
    }
}

extern "C" void kernel_launch(void* const* d_in, const int* in_sizes, int n_in,
                              void* d_out, int out_size) {
    (void)n_in; (void)out_size;
    const float* inp   = (const float*)d_in[1];
    const float* t1i   = (const float*)d_in[2];
    const float* b1i   = (const float*)d_in[3];
    const float* t2i   = (const float*)d_in[4];
    const float* b2i   = (const float*)d_in[5];
    const float* invK  = (const float*)d_in[6];
    const float* invKb = (const float*)d_in[7];
    int K = in_sizes[1] / 6;

    zero_kernel<<<1, 1024>>>();
    mega_kernel<<<NBLK, NTHR>>>(inp, t1i, b1i, t2i, b2i, invK, invKb, (float*)d_out, K);
}